// round 3
// baseline (speedup 1.0000x reference)
#include <cuda_runtime.h>

// ---------------------------------------------------------------------------
// EvalNet: EmbeddingBag(sum,pad) -> screlu -> fc2(1024->32) -> screlu
//          -> bucketed cp/wdl heads.
// K1: column-chunked gather, 64-col table slice in SMEM (conflict-free
//     LDS.128), writes screlu'd h to global scratch. Per-block dtype sniff.
// K2: fc2 via packed fma.rn.f32x2 (sample pairs in 64-bit lanes, duplicated
//     weights), then heads. 2 CTAs/SM for stage/compute overlap.
// ---------------------------------------------------------------------------

#define HIDDEN   1024
#define NROWS    769
#define CHUNK    64
#define NCHUNKS  (HIDDEN / CHUNK)   // 16
#define NGROUPS  9                  // 16*9 = 144 blocks
#define K1T      512
#define TILE     32
#define MAX_B    16384

#define K2T      256
#define TS2      64                 // samples per K2 block
#define HP_STRIDE 66                // h_pair row stride (float2)
#define WD_STRIDE 34                // wdup  row stride (float2)

__device__ float g_h[(size_t)MAX_B * HIDDEN];   // screlu'd hidden, fp32

__device__ __forceinline__ float screlu1(float v)
{
    float c = fminf(fmaxf(v, 0.0f), 1.0f);
    return c * c;
}

__device__ __forceinline__ void fma2(unsigned long long& acc,
                                     unsigned long long a,
                                     unsigned long long b)
{
    asm("fma.rn.f32x2 %0, %1, %2, %0;" : "+l"(acc) : "l"(a), "l"(b));
}

// ---------------------------------------------------------------------------
// K1: gather + bias + screlu for a 64-column slice.
// grid = (NCHUNKS, NGROUPS); block = 512.
// Thread (s = tid/16, q = tid%16) accumulates float4 cols [q*4, q*4+4)
// for sample s of the current 32-sample tile. Gather is conflict-free LDS.128.
// ---------------------------------------------------------------------------
__global__ __launch_bounds__(K1T)
void gather_kernel(const void* __restrict__ xv,
                   const float* __restrict__ emb,
                   const float* __restrict__ bias1,
                   int B)
{
    extern __shared__ char smem[];
    float* s_tab  = (float*)smem;                                        // NROWS*CHUNK
    int*   s_idx  = (int*)(smem + NROWS * CHUNK * 4);                    // TILE*32
    float* s_bias = (float*)(smem + NROWS * CHUNK * 4 + TILE * 32 * 4);  // CHUNK
    int*   s_nz   = (int*)(smem + NROWS * CHUNK * 4 + TILE * 32 * 4 + CHUNK * 4);

    const int tid   = threadIdx.x;
    const int cbase = blockIdx.x * CHUNK;

    if (tid == 0) *s_nz = 0;
    __syncthreads();

    // dtype sniff: int64 indices => every odd 32-bit word is zero
    if (tid < 64) {
        if (((const unsigned int*)xv)[2 * tid + 1]) atomicOr(s_nz, 1);
    }

    // Stage the table slice: 769 rows x 64 cols.
    const float4* embv = (const float4*)emb;
    float4*       tabv = (float4*)s_tab;
    for (int i = tid; i < NROWS * (CHUNK / 4); i += K1T) {
        int row = i / (CHUNK / 4);
        int c4  = i % (CHUNK / 4);
        tabv[i] = embv[row * (HIDDEN / 4) + (cbase / 4) + c4];
    }
    if (tid < CHUNK) s_bias[tid] = bias1[cbase + tid];
    __syncthreads();

    const int is64 = (*s_nz == 0);

    const int s = tid >> 4;     // sample within tile
    const int q = tid & 15;     // float4 column group

    const int spg     = (B + NGROUPS - 1) / NGROUPS;
    const int s_begin = blockIdx.y * spg;
    const int s_end   = min(B, s_begin + spg);

    const int*       x32 = (const int*)xv;
    const long long* x64 = (const long long*)xv;

    for (int t0 = s_begin; t0 < s_end; t0 += TILE) {
        __syncthreads();
        for (int i = tid; i < TILE * 32; i += K1T) {
            int samp = t0 + (i >> 5);
            int v = NROWS - 1;
            if (samp < B) {
                int r = i & 31;
                v = is64 ? (int)x64[(size_t)samp * 32 + r]
                         : x32[samp * 32 + r];
            }
            s_idx[i] = v;
        }
        __syncthreads();

        int samp = t0 + s;
        if (samp < B) {
            float4 acc = make_float4(0.f, 0.f, 0.f, 0.f);
            #pragma unroll
            for (int r0 = 0; r0 < 32; r0 += 8) {
                int id[8];
                #pragma unroll
                for (int k = 0; k < 8; k++) id[k] = s_idx[s * 32 + r0 + k];
                #pragma unroll
                for (int k = 0; k < 8; k++) {
                    float4 v = tabv[id[k] * (CHUNK / 4) + q];
                    acc.x += v.x; acc.y += v.y; acc.z += v.z; acc.w += v.w;
                }
            }
            float4 b = ((const float4*)s_bias)[q];
            acc.x = screlu1(acc.x + b.x);
            acc.y = screlu1(acc.y + b.y);
            acc.z = screlu1(acc.z + b.z);
            acc.w = screlu1(acc.w + b.w);
            ((float4*)(g_h + (size_t)samp * HIDDEN + cbase))[q] = acc;
        }
    }
}

// ---------------------------------------------------------------------------
// K2: h2 = screlu(h @ fc2_w^T + fc2_b) via packed f32x2 FMA, then heads.
// 256 threads, 64 samples/block. Thread (sg, jq) owns sample pair
// (2sg, 2sg+1) and j = jq*4..jq*4+3; accumulators are f32x2 sample pairs.
// ---------------------------------------------------------------------------
__global__ __launch_bounds__(K2T)
void fc_kernel(const void* __restrict__ xv,
               const float* __restrict__ fc2_w, const float* __restrict__ fc2_b,
               const float* __restrict__ cp_w,  const float* __restrict__ cp_b,
               const float* __restrict__ wdl_w, const float* __restrict__ wdl_b,
               const void* __restrict__ pcv, float* __restrict__ out, int B)
{
    __shared__ float2 h_pair[32 * HP_STRIDE];   // [sg][c] interleaved sample pair
    __shared__ float2 wdup[64 * WD_STRIDE];     // [c][j], (w,w) duplicated
    __shared__ float  s_cp_w[8 * 32];
    __shared__ float  s_wdl_w[24 * 32];
    __shared__ float  s_cp_b[8];
    __shared__ float  s_wdl_b[24];
    __shared__ float  s_fc2_b[32];
    __shared__ int    s_nz;

    const int tid = threadIdx.x;
    const int s0  = blockIdx.x * TS2;

    if (tid == 0) s_nz = 0;
    __syncthreads();
    if (tid < 64) {
        if (((const unsigned int*)xv)[2 * tid + 1]) atomicOr(&s_nz, 1);
    }
    // head weights
    for (int i = tid; i < 8 * 32; i += K2T)  s_cp_w[i]  = cp_w[i];
    for (int i = tid; i < 24 * 32; i += K2T) s_wdl_w[i] = wdl_w[i];
    if (tid < 8)  s_cp_b[tid]  = cp_b[tid];
    if (tid < 24) s_wdl_b[tid] = wdl_b[tid];
    if (tid < 32) s_fc2_b[tid] = fc2_b[tid];

    const int jq = tid & 7;      // j group (4 j's)
    const int sg = tid >> 3;     // sample-pair index 0..31

    unsigned long long acc[4] = {0ull, 0ull, 0ull, 0ull};

    for (int c0 = 0; c0 < HIDDEN; c0 += 64) {
        __syncthreads();
        // stage duplicated weights: wdup[c][j] = (w[j][c0+c], w[j][c0+c])
        #pragma unroll
        for (int r = 0; r < 8; r++) {
            int i = tid + r * K2T;
            int c = i & 63, j = i >> 6;
            float w = fc2_w[j * HIDDEN + c0 + c];
            wdup[c * WD_STRIDE + j] = make_float2(w, w);
        }
        // stage h sample pairs (coalesced float4 reads, STS.128 writes)
        #pragma unroll
        for (int r = 0; r < 2; r++) {
            int i  = tid + r * K2T;
            int c4 = i & 15, g = i >> 4;     // g = sample-pair 0..31
            const float4 a = *(const float4*)(g_h + (size_t)(s0 + g * 2)     * HIDDEN + c0 + c4 * 4);
            const float4 b = *(const float4*)(g_h + (size_t)(s0 + g * 2 + 1) * HIDDEN + c0 + c4 * 4);
            float4* dst = (float4*)&h_pair[g * HP_STRIDE + c4 * 4];
            dst[0] = make_float4(a.x, b.x, a.y, b.y);
            dst[1] = make_float4(a.z, b.z, a.w, b.w);
        }
        __syncthreads();

        const unsigned long long* hrow =
            (const unsigned long long*)&h_pair[sg * HP_STRIDE];
        #pragma unroll 8
        for (int c = 0; c < 64; c++) {
            unsigned long long hv = hrow[c];
            const ulonglong2* wp =
                (const ulonglong2*)&wdup[c * WD_STRIDE + jq * 4];
            ulonglong2 w01 = wp[0];
            ulonglong2 w23 = wp[1];
            fma2(acc[0], hv, w01.x);
            fma2(acc[1], hv, w01.y);
            fma2(acc[2], hv, w23.x);
            fma2(acc[3], hv, w23.y);
        }
    }

    // h2 to SMEM (reuse h_pair region: 64*33*4 B <= 16896 B)
    __syncthreads();
    float* s_h2 = (float*)h_pair;
    #pragma unroll
    for (int jj = 0; jj < 4; jj++) {
        int j = jq * 4 + jj;
        float lo = __uint_as_float((unsigned)(acc[jj] & 0xffffffffull));
        float hi = __uint_as_float((unsigned)(acc[jj] >> 32));
        s_h2[(sg * 2)     * 33 + j] = screlu1(lo + s_fc2_b[j]);
        s_h2[(sg * 2 + 1) * 33 + j] = screlu1(hi + s_fc2_b[j]);
    }
    __syncthreads();

    // heads: one thread per sample
    if (tid < TS2) {
        int samp = s0 + tid;
        if (samp < B) {
            const int is64 = (s_nz == 0);
            int pc = is64 ? (int)((const long long*)pcv)[samp]
                          : ((const int*)pcv)[samp];
            int bkt = (pc - 2) * 8 / 30;
            bkt = max(0, min(7, bkt));

            const float* h2 = &s_h2[tid * 33];
            float cp = s_cp_b[bkt];
            float w0 = s_wdl_b[bkt * 3 + 0];
            float w1 = s_wdl_b[bkt * 3 + 1];
            float w2 = s_wdl_b[bkt * 3 + 2];
            const float* cw  = &s_cp_w[bkt * 32];
            const float* ww0 = &s_wdl_w[(bkt * 3 + 0) * 32];
            const float* ww1 = &s_wdl_w[(bkt * 3 + 1) * 32];
            const float* ww2 = &s_wdl_w[(bkt * 3 + 2) * 32];
            #pragma unroll
            for (int j = 0; j < 32; j++) {
                float hh = h2[j];
                cp = fmaf(hh, cw[j],  cp);
                w0 = fmaf(hh, ww0[j], w0);
                w1 = fmaf(hh, ww1[j], w1);
                w2 = fmaf(hh, ww2[j], w2);
            }
            out[samp] = cp;
            out[B + samp * 3 + 0] = w0;
            out[B + samp * 3 + 1] = w1;
            out[B + samp * 3 + 2] = w2;
        }
    }
}

// ---------------------------------------------------------------------------
extern "C" void kernel_launch(void* const* d_in, const int* in_sizes, int n_in,
                              void* d_out, int out_size)
{
    const void*  x      = d_in[0];
    const void*  pc     = d_in[1];
    const float* emb    = (const float*)d_in[2];
    const float* bias1  = (const float*)d_in[3];
    const float* fc2_w  = (const float*)d_in[4];
    const float* fc2_b  = (const float*)d_in[5];
    const float* cp_w   = (const float*)d_in[6];
    const float* cp_b   = (const float*)d_in[7];
    const float* wdl_w  = (const float*)d_in[8];
    const float* wdl_b  = (const float*)d_in[9];

    int B = in_sizes[0] / 32;
    if (B > MAX_B) B = MAX_B;

    const int k1_smem = NROWS * CHUNK * 4 + TILE * 32 * 4 + CHUNK * 4 + 16;
    cudaFuncSetAttribute(gather_kernel,
                         cudaFuncAttributeMaxDynamicSharedMemorySize, k1_smem);
    dim3 g1(NCHUNKS, NGROUPS);
    gather_kernel<<<g1, K1T, k1_smem>>>(x, emb, bias1, B);

    int g2 = (B + TS2 - 1) / TS2;
    fc_kernel<<<g2, K2T>>>(x, fc2_w, fc2_b, cp_w, cp_b, wdl_w, wdl_b,
                           pc, (float*)d_out, B);
}

// round 5
// speedup vs baseline: 1.6789x; 1.6789x over previous
#include <cuda_runtime.h>
#include <cstdint>

// ---------------------------------------------------------------------------
// EvalNet: EmbeddingBag(sum,pad) -> screlu -> fc2(1024->32) -> screlu
//          -> bucketed cp/wdl heads.
// K1: column-chunked SMEM gather; f32x2 accumulation; writes h
//     PAIR-INTERLEAVED: g_hp[pair][c] = (h[2p][c], h[2p+1][c]) via shfl.
//     Sample-group starts are 32-aligned so pairing is globally consistent.
// K2: cp.async double-buffered fc2; sample-pair FFMA2 inner loop; heads.
// ---------------------------------------------------------------------------

#define HIDDEN   1024
#define NROWS    769
#define CHUNK    64
#define NCHUNKS  (HIDDEN / CHUNK)   // 16
#define NGROUPS  9                  // 16*9 = 144 blocks
#define K1T      512
#define TILE     32
#define MAX_B    16384

#define K2T      256
#define TS2      64                 // samples per K2 block
#define WT_STRIDE 33                // weight row stride (floats): 33 % 32 == 1

__device__ float g_h[(size_t)MAX_B * HIDDEN];   // pair-interleaved hidden

__device__ __forceinline__ float screlu1(float v)
{
    float c = fminf(fmaxf(v, 0.0f), 1.0f);
    return c * c;
}

__device__ __forceinline__ void fma2(unsigned long long& acc,
                                     unsigned long long a,
                                     unsigned long long b)
{
    asm("fma.rn.f32x2 %0, %1, %2, %0;" : "+l"(acc) : "l"(a), "l"(b));
}

__device__ __forceinline__ void add2(unsigned long long& acc,
                                     unsigned long long v)
{
    asm("add.rn.f32x2 %0, %0, %1;" : "+l"(acc) : "l"(v));
}

__device__ __forceinline__ unsigned long long packdup(float w)
{
    unsigned long long r;
    asm("mov.b64 %0, {%1, %1};" : "=l"(r) : "f"(w));
    return r;
}

__device__ __forceinline__ uint32_t smem_u32(const void* p)
{
    uint32_t a;
    asm("{ .reg .u64 t; cvta.to.shared.u64 t, %1; cvt.u32.u64 %0, t; }"
        : "=r"(a) : "l"(p));
    return a;
}

__device__ __forceinline__ void cp_async16(uint32_t dst, const void* src)
{
    asm volatile("cp.async.ca.shared.global [%0], [%1], 16;"
                 :: "r"(dst), "l"(__cvta_generic_to_global(src)));
}

__device__ __forceinline__ void cp_async4(uint32_t dst, const void* src)
{
    asm volatile("cp.async.ca.shared.global [%0], [%1], 4;"
                 :: "r"(dst), "l"(__cvta_generic_to_global(src)));
}

#define CP_COMMIT() asm volatile("cp.async.commit_group;" ::: "memory")
#define CP_WAIT0()  asm volatile("cp.async.wait_group 0;" ::: "memory")

union F4U {
    float4 f;
    unsigned long long u[2];
};

// ---------------------------------------------------------------------------
// K1: gather + bias + screlu for a 64-column slice; pair-interleaved output.
// ---------------------------------------------------------------------------
__global__ __launch_bounds__(K1T)
void gather_kernel(const void* __restrict__ xv,
                   const float* __restrict__ emb,
                   const float* __restrict__ bias1,
                   int B)
{
    extern __shared__ char smem[];
    float* s_tab  = (float*)smem;                                        // NROWS*CHUNK
    int*   s_idx  = (int*)(smem + NROWS * CHUNK * 4);                    // TILE*32
    float* s_bias = (float*)(smem + NROWS * CHUNK * 4 + TILE * 32 * 4);  // CHUNK
    int*   s_nz   = (int*)(smem + NROWS * CHUNK * 4 + TILE * 32 * 4 + CHUNK * 4);

    const int tid   = threadIdx.x;
    const int cbase = blockIdx.x * CHUNK;

    if (tid == 0) *s_nz = 0;
    __syncthreads();

    // dtype sniff: int64 indices => every odd 32-bit word is zero
    if (tid < 64) {
        if (((const unsigned int*)xv)[2 * tid + 1]) atomicOr(s_nz, 1);
    }

    // Stage the table slice: 769 rows x 64 cols.
    const float4* embv = (const float4*)emb;
    float4*       tabv = (float4*)s_tab;
    for (int i = tid; i < NROWS * (CHUNK / 4); i += K1T) {
        int row = i / (CHUNK / 4);
        int c4  = i % (CHUNK / 4);
        tabv[i] = embv[row * (HIDDEN / 4) + (cbase / 4) + c4];
    }
    if (tid < CHUNK) s_bias[tid] = bias1[cbase + tid];
    __syncthreads();

    const int is64 = (*s_nz == 0);

    const int s   = tid >> 4;     // sample within tile (0..31)
    const int q   = tid & 15;     // float4 column group
    const int odd = s & 1;

    // TILE-aligned group starts => t0 always even => pairing consistent.
    const int spg     = (((B + NGROUPS - 1) / NGROUPS) + TILE - 1) & ~(TILE - 1);
    const int s_begin = blockIdx.y * spg;
    const int s_end   = min(B, s_begin + spg);

    const int*       x32 = (const int*)xv;
    const long long* x64 = (const long long*)xv;
    float2*          ghp = (float2*)g_h;

    for (int t0 = s_begin; t0 < s_end; t0 += TILE) {
        __syncthreads();
        for (int i = tid; i < TILE * 32; i += K1T) {
            int samp = t0 + (i >> 5);
            int v = NROWS - 1;                  // pad row if OOB
            if (samp < B) {
                int r = i & 31;
                v = is64 ? (int)x64[(size_t)samp * 32 + r]
                         : x32[samp * 32 + r];
            }
            s_idx[i] = v;
        }
        __syncthreads();

        int samp = t0 + s;

        unsigned long long a01 = 0ull, a23 = 0ull;
        #pragma unroll
        for (int r0 = 0; r0 < 32; r0 += 8) {
            int id[8];
            #pragma unroll
            for (int k = 0; k < 8; k++) id[k] = s_idx[s * 32 + r0 + k];
            #pragma unroll
            for (int k = 0; k < 8; k++) {
                F4U v;
                v.f = tabv[id[k] * (CHUNK / 4) + q];
                add2(a01, v.u[0]);
                add2(a23, v.u[1]);
            }
        }

        F4U r;
        r.u[0] = a01;
        r.u[1] = a23;
        float4 b = ((const float4*)s_bias)[q];
        float4 h4;
        h4.x = screlu1(r.f.x + b.x);
        h4.y = screlu1(r.f.y + b.y);
        h4.z = screlu1(r.f.z + b.z);
        h4.w = screlu1(r.f.w + b.w);

        // pair exchange: partner sample = s^1 -> lane^16 (same warp)
        float4 p4;
        p4.x = __shfl_xor_sync(0xffffffffu, h4.x, 16);
        p4.y = __shfl_xor_sync(0xffffffffu, h4.y, 16);
        p4.z = __shfl_xor_sync(0xffffffffu, h4.z, 16);
        p4.w = __shfl_xor_sync(0xffffffffu, h4.w, 16);

        if (samp < B) {
            size_t pr = (size_t)(samp >> 1);
            // even thread writes cols 4q,4q+1 ; odd writes 4q+2,4q+3
            float4 outv = odd ? make_float4(p4.z, h4.z, p4.w, h4.w)
                              : make_float4(h4.x, p4.x, h4.y, p4.y);
            *(float4*)(ghp + pr * HIDDEN + (cbase + 4 * q + odd * 2)) = outv;
        }
    }
}

// ---------------------------------------------------------------------------
// K2: fc2 via sample-pair FFMA2 with cp.async double-buffered staging; heads.
// 256 threads, 64 samples/block. sg = tid>>4 owns samples 4sg..4sg+3
// (pairs 2sg, 2sg+1); jq = tid&15 owns j = 2jq, 2jq+1.
// ---------------------------------------------------------------------------
#define K2_OFF_H    0
#define K2_HBUF     16384
#define K2_OFF_W    32768
#define K2_WBUF     8448
#define K2_OFF_CPW  49664
#define K2_OFF_WDLW 50688
#define K2_OFF_FB   53760
#define K2_OFF_CB   53888
#define K2_OFF_WB   53920
#define K2_OFF_NZ   54016
#define K2_SMEM     54032

__global__ __launch_bounds__(K2T)
void fc_kernel(const void* __restrict__ xv,
               const float* __restrict__ fc2_w, const float* __restrict__ fc2_b,
               const float* __restrict__ cp_w,  const float* __restrict__ cp_b,
               const float* __restrict__ wdl_w, const float* __restrict__ wdl_b,
               const void* __restrict__ pcv, float* __restrict__ out, int B)
{
    extern __shared__ char smem[];
    const uint32_t sbase = smem_u32(smem);

    float* s_cp_w  = (float*)(smem + K2_OFF_CPW);
    float* s_wdl_w = (float*)(smem + K2_OFF_WDLW);
    float* s_fc2_b = (float*)(smem + K2_OFF_FB);
    float* s_cp_b  = (float*)(smem + K2_OFF_CB);
    float* s_wdl_b = (float*)(smem + K2_OFF_WB);
    int*   s_nz    = (int*)(smem + K2_OFF_NZ);

    const int tid = threadIdx.x;
    const int s0  = blockIdx.x * TS2;
    const int p0  = s0 >> 1;              // first pair row

    if (tid == 0) *s_nz = 0;
    __syncthreads();
    if (tid < 64) {
        if (((const unsigned int*)xv)[2 * tid + 1]) atomicOr(s_nz, 1);
    }
    for (int i = tid; i < 8 * 32; i += K2T)  s_cp_w[i]  = cp_w[i];
    for (int i = tid; i < 24 * 32; i += K2T) s_wdl_w[i] = wdl_w[i];
    if (tid < 32) s_fc2_b[tid] = fc2_b[tid];
    if (tid < 8)  s_cp_b[tid]  = cp_b[tid];
    if (tid < 24) s_wdl_b[tid] = wdl_b[tid];

    const float2* ghp = (const float2*)g_h;

    auto stage = [&](int k) {
        int buf = k & 1;
        int c0  = k * CHUNK;
        uint32_t hdst = sbase + K2_OFF_H + buf * K2_HBUF;
        uint32_t wdst = sbase + K2_OFF_W + buf * K2_WBUF;
        #pragma unroll
        for (int r = 0; r < 4; r++) {
            int u   = tid + r * K2T;
            int p   = u >> 5;            // 0..31
            int c16 = u & 31;            // 0..31 (2 float2 each)
            cp_async16(hdst + (uint32_t)(p * 512 + c16 * 16),
                       ghp + ((size_t)(p0 + p) * HIDDEN + c0 + c16 * 2));
        }
        #pragma unroll
        for (int r = 0; r < 8; r++) {
            int u = tid + r * K2T;
            int j = u >> 6;              // 0..31
            int c = u & 63;              // 0..63
            cp_async4(wdst + (uint32_t)((c * WT_STRIDE + j) * 4),
                      fc2_w + j * HIDDEN + c0 + c);
        }
        CP_COMMIT();
    };

    stage(0);

    const int jq = tid & 15;     // j = 2jq, 2jq+1
    const int sg = tid >> 4;     // samples 4sg..4sg+3 -> pairs 2sg, 2sg+1

    unsigned long long acc00 = 0ull, acc01 = 0ull, acc10 = 0ull, acc11 = 0ull;

    for (int k = 0; k < NCHUNKS; k++) {
        CP_WAIT0();
        __syncthreads();
        if (k + 1 < NCHUNKS) stage(k + 1);   // overlap with compute below

        int buf = k & 1;
        const unsigned long long* hb =
            (const unsigned long long*)(smem + K2_OFF_H + buf * K2_HBUF);
        const float* wb = (const float*)(smem + K2_OFF_W + buf * K2_WBUF);
        const unsigned long long* h0 = hb + (2 * sg) * CHUNK;
        const unsigned long long* h1 = hb + (2 * sg + 1) * CHUNK;

        #pragma unroll 8
        for (int c = 0; c < CHUNK; c++) {
            unsigned long long hv0 = h0[c];
            unsigned long long hv1 = h1[c];
            unsigned long long W0 = packdup(wb[c * WT_STRIDE + 2 * jq]);
            unsigned long long W1 = packdup(wb[c * WT_STRIDE + 2 * jq + 1]);
            fma2(acc00, hv0, W0);
            fma2(acc01, hv0, W1);
            fma2(acc10, hv1, W0);
            fma2(acc11, hv1, W1);
        }
        __syncthreads();   // everyone done with buf before it's re-staged
    }

    // h2 = screlu(acc + b) into smem (reuse hbuf[0]; 64*33*4 = 8448 B)
    float* s_h2 = (float*)(smem + K2_OFF_H);
    {
        unsigned long long accs[2][2] = {{acc00, acc01}, {acc10, acc11}};
        #pragma unroll
        for (int p = 0; p < 2; p++) {
            #pragma unroll
            for (int jj = 0; jj < 2; jj++) {
                int j = 2 * jq + jj;
                float lo = __uint_as_float((unsigned)(accs[p][jj] & 0xffffffffull));
                float hi = __uint_as_float((unsigned)(accs[p][jj] >> 32));
                s_h2[(4 * sg + 2 * p)     * 33 + j] = screlu1(lo + s_fc2_b[j]);
                s_h2[(4 * sg + 2 * p + 1) * 33 + j] = screlu1(hi + s_fc2_b[j]);
            }
        }
    }
    __syncthreads();

    // heads: one thread per sample
    if (tid < TS2) {
        int samp = s0 + tid;
        if (samp < B) {
            const int is64 = (*s_nz == 0);
            int pc = is64 ? (int)((const long long*)pcv)[samp]
                          : ((const int*)pcv)[samp];
            int bkt = (pc - 2) * 8 / 30;
            bkt = max(0, min(7, bkt));

            const float* h2 = &s_h2[tid * 33];
            float cp = s_cp_b[bkt];
            float w0 = s_wdl_b[bkt * 3 + 0];
            float w1 = s_wdl_b[bkt * 3 + 1];
            float w2 = s_wdl_b[bkt * 3 + 2];
            const float* cw  = &s_cp_w[bkt * 32];
            const float* ww0 = &s_wdl_w[(bkt * 3 + 0) * 32];
            const float* ww1 = &s_wdl_w[(bkt * 3 + 1) * 32];
            const float* ww2 = &s_wdl_w[(bkt * 3 + 2) * 32];
            #pragma unroll
            for (int j = 0; j < 32; j++) {
                float hh = h2[j];
                cp = fmaf(hh, cw[j],  cp);
                w0 = fmaf(hh, ww0[j], w0);
                w1 = fmaf(hh, ww1[j], w1);
                w2 = fmaf(hh, ww2[j], w2);
            }
            out[samp] = cp;
            out[B + samp * 3 + 0] = w0;
            out[B + samp * 3 + 1] = w1;
            out[B + samp * 3 + 2] = w2;
        }
    }
}

// ---------------------------------------------------------------------------
extern "C" void kernel_launch(void* const* d_in, const int* in_sizes, int n_in,
                              void* d_out, int out_size)
{
    const void*  x      = d_in[0];
    const void*  pc     = d_in[1];
    const float* emb    = (const float*)d_in[2];
    const float* bias1  = (const float*)d_in[3];
    const float* fc2_w  = (const float*)d_in[4];
    const float* fc2_b  = (const float*)d_in[5];
    const float* cp_w   = (const float*)d_in[6];
    const float* cp_b   = (const float*)d_in[7];
    const float* wdl_w  = (const float*)d_in[8];
    const float* wdl_b  = (const float*)d_in[9];

    int B = in_sizes[0] / 32;
    if (B > MAX_B) B = MAX_B;

    const int k1_smem = NROWS * CHUNK * 4 + TILE * 32 * 4 + CHUNK * 4 + 16;
    cudaFuncSetAttribute(gather_kernel,
                         cudaFuncAttributeMaxDynamicSharedMemorySize, k1_smem);
    dim3 g1(NCHUNKS, NGROUPS);
    gather_kernel<<<g1, K1T, k1_smem>>>(x, emb, bias1, B);

    cudaFuncSetAttribute(fc_kernel,
                         cudaFuncAttributeMaxDynamicSharedMemorySize, K2_SMEM);
    int g2 = (B + TS2 - 1) / TS2;
    fc_kernel<<<g2, K2T, K2_SMEM>>>(x, fc2_w, fc2_b, cp_w, cp_b, wdl_w, wdl_b,
                                    pc, (float*)d_out, B);
}

// round 6
// speedup vs baseline: 2.6167x; 1.5586x over previous
#include <cuda_runtime.h>
#include <cuda_fp16.h>
#include <cstdint>

// ---------------------------------------------------------------------------
// EvalNet: EmbeddingBag(sum,pad) -> screlu -> fc2(1024->32) -> screlu
//          -> bucketed cp/wdl heads.
// K0: convert emb table fp32 -> fp16 (pad row stays exactly 0).
// K1: 128-col chunked SMEM gather over the fp16 table; HADD2 row-pairing,
//     fp32 (f32x2) accumulation; register-prefetched double-buffered indices;
//     writes h PAIR-INTERLEAVED: ghp[pair][c] = (h[2p][c], h[2p+1][c]).
// K2: cp.async double-buffered fc2 with sample-pair FFMA2; bucketed heads.
// ---------------------------------------------------------------------------

#define HIDDEN   1024
#define NROWS    769
#define MAX_B    16384
#define TILE     32

#define CHUNK1   128
#define NCHUNKS1 (HIDDEN / CHUNK1)   // 8
#define NGROUPS1 18                  // 8*18 = 144 blocks
#define K1T      512

#define K2T      256
#define TS2      64
#define NCHUNKS2 16
#define CHUNK2   64
#define WT_STRIDE 33

__device__ float  g_h[(size_t)MAX_B * HIDDEN];     // pair-interleaved hidden
__device__ __half g_emb_h[NROWS * HIDDEN];         // fp16 table

__device__ __forceinline__ float screlu1(float v)
{
    float c = fminf(fmaxf(v, 0.0f), 1.0f);
    return c * c;
}

__device__ __forceinline__ void fma2(unsigned long long& acc,
                                     unsigned long long a,
                                     unsigned long long b)
{
    asm("fma.rn.f32x2 %0, %1, %2, %0;" : "+l"(acc) : "l"(a), "l"(b));
}

__device__ __forceinline__ void add2(unsigned long long& acc,
                                     unsigned long long v)
{
    asm("add.rn.f32x2 %0, %0, %1;" : "+l"(acc) : "l"(v));
}

__device__ __forceinline__ unsigned long long packdup(float w)
{
    unsigned long long r;
    asm("mov.b64 %0, {%1, %1};" : "=l"(r) : "f"(w));
    return r;
}

__device__ __forceinline__ uint32_t smem_u32(const void* p)
{
    uint32_t a;
    asm("{ .reg .u64 t; cvta.to.shared.u64 t, %1; cvt.u32.u64 %0, t; }"
        : "=r"(a) : "l"(p));
    return a;
}

__device__ __forceinline__ void cp_async16(uint32_t dst, const void* src)
{
    asm volatile("cp.async.ca.shared.global [%0], [%1], 16;"
                 :: "r"(dst), "l"(__cvta_generic_to_global(src)));
}

__device__ __forceinline__ void cp_async4(uint32_t dst, const void* src)
{
    asm volatile("cp.async.ca.shared.global [%0], [%1], 4;"
                 :: "r"(dst), "l"(__cvta_generic_to_global(src)));
}

#define CP_COMMIT() asm volatile("cp.async.commit_group;" ::: "memory")
#define CP_WAIT0()  asm volatile("cp.async.wait_group 0;" ::: "memory")

union F2U { float2 f; unsigned long long u; };

// ---------------------------------------------------------------------------
// K0: fp32 -> fp16 table conversion.
// ---------------------------------------------------------------------------
__global__ __launch_bounds__(512)
void convert_kernel(const float* __restrict__ emb)
{
    int i = blockIdx.x * 512 + threadIdx.x;        // half2 units
    if (i < NROWS * HIDDEN / 2) {
        float2 v = ((const float2*)emb)[i];
        ((__half2*)g_emb_h)[i] = __floats2half2_rn(v.x, v.y);
    }
}

// ---------------------------------------------------------------------------
// K1: gather + bias + screlu over a 128-col fp16 table slice.
// grid = (NCHUNKS1, NGROUPS1); block = 512.
// Thread (s = tid>>4, q = tid&15) owns cols 8q..8q+7 of sample s in the
// 32-sample tile. Per row: one LDS.128 (8 halves); rows combined in pairs
// with HADD2 then accumulated f32x2.
// ---------------------------------------------------------------------------
__global__ __launch_bounds__(K1T)
void gather_kernel(const void* __restrict__ xv,
                   const float* __restrict__ bias1,
                   int B)
{
    extern __shared__ char smem[];
    __half* s_tab  = (__half*)smem;                                  // NROWS*CHUNK1*2
    int*    s_idx  = (int*)(smem + NROWS * CHUNK1 * 2);              // 2*1024*4
    float*  s_bias = (float*)(smem + NROWS * CHUNK1 * 2 + 8192);     // CHUNK1*4
    int*    s_nz   = (int*)(smem + NROWS * CHUNK1 * 2 + 8192 + CHUNK1 * 4);

    const int tid   = threadIdx.x;
    const int cbase = blockIdx.x * CHUNK1;

    if (tid == 0) *s_nz = 0;
    __syncthreads();

    // dtype sniff: int64 indices => every odd 32-bit word is zero
    if (tid < 64) {
        if (((const unsigned int*)xv)[2 * tid + 1]) atomicOr(s_nz, 1);
    }

    // Stage the fp16 table slice: 769 rows x 128 cols = 16 uint4 per row.
    {
        const uint4* src = (const uint4*)g_emb_h;       // row stride 128 uint4
        uint4*       dst = (uint4*)s_tab;               // row stride 16 uint4
        const int cb8 = cbase >> 3;
        for (int i = tid; i < NROWS * 16; i += K1T) {
            int row = i >> 4, u = i & 15;
            dst[i] = src[row * 128 + cb8 + u];
        }
    }
    if (tid < CHUNK1) s_bias[tid] = bias1[cbase + tid];
    __syncthreads();

    const int is64 = (*s_nz == 0);

    const int s   = tid >> 4;
    const int q   = tid & 15;
    const int odd = s & 1;

    const int spg     = (((B + NGROUPS1 - 1) / NGROUPS1) + TILE - 1) & ~(TILE - 1);
    const int s_begin = blockIdx.y * spg;
    const int s_end   = min(B, s_begin + spg);

    const int*       x32 = (const int*)xv;
    const long long* x64 = (const long long*)xv;
    float2*          ghp = (float2*)g_h;
    const uint4*     tab4 = (const uint4*)s_tab;

    // preload first tile's indices into registers (2 per thread)
    int pre0 = NROWS - 1, pre1 = NROWS - 1;
    if (s_begin < s_end) {
        #pragma unroll
        for (int k = 0; k < 2; k++) {
            int j = tid + k * K1T;
            int samp = s_begin + (j >> 5);
            int v = NROWS - 1;
            if (samp < B) {
                int r = j & 31;
                v = is64 ? (int)x64[(size_t)samp * 32 + r]
                         : x32[samp * 32 + r];
            }
            if (k == 0) pre0 = v; else pre1 = v;
        }
    }

    int buf = 0;
    for (int t0 = s_begin; t0 < s_end; t0 += TILE) {
        s_idx[buf * 1024 + tid]       = pre0;
        s_idx[buf * 1024 + tid + K1T] = pre1;
        __syncthreads();

        // prefetch next tile's indices (overlaps with gather below)
        int tn = t0 + TILE;
        if (tn < s_end) {
            #pragma unroll
            for (int k = 0; k < 2; k++) {
                int j = tid + k * K1T;
                int samp = tn + (j >> 5);
                int v = NROWS - 1;
                if (samp < B) {
                    int r = j & 31;
                    v = is64 ? (int)x64[(size_t)samp * 32 + r]
                             : x32[samp * 32 + r];
                }
                if (k == 0) pre0 = v; else pre1 = v;
            }
        }

        const int* idx = &s_idx[buf * 1024 + s * 32];

        unsigned long long a0 = 0ull, a1 = 0ull, a2 = 0ull, a3 = 0ull;
        #pragma unroll
        for (int r0 = 0; r0 < 32; r0 += 8) {
            int id[8];
            #pragma unroll
            for (int k = 0; k < 8; k++) id[k] = idx[r0 + k];
            uint4 v[8];
            #pragma unroll
            for (int k = 0; k < 8; k++) v[k] = tab4[id[k] * 16 + q];
            #pragma unroll
            for (int p = 0; p < 4; p++) {
                const uint4& va = v[2 * p];
                const uint4& vb = v[2 * p + 1];
                __half2 hx = __hadd2(*(const __half2*)&va.x, *(const __half2*)&vb.x);
                __half2 hy = __hadd2(*(const __half2*)&va.y, *(const __half2*)&vb.y);
                __half2 hz = __hadd2(*(const __half2*)&va.z, *(const __half2*)&vb.z);
                __half2 hw = __hadd2(*(const __half2*)&va.w, *(const __half2*)&vb.w);
                F2U f0, f1, f2, f3;
                f0.f = __half22float2(hx);
                f1.f = __half22float2(hy);
                f2.f = __half22float2(hz);
                f3.f = __half22float2(hw);
                add2(a0, f0.u);
                add2(a1, f1.u);
                add2(a2, f2.u);
                add2(a3, f3.u);
            }
        }

        // bias + screlu
        float h[8];
        {
            F2U u0, u1, u2, u3;
            u0.u = a0; u1.u = a1; u2.u = a2; u3.u = a3;
            h[0] = u0.f.x; h[1] = u0.f.y; h[2] = u1.f.x; h[3] = u1.f.y;
            h[4] = u2.f.x; h[5] = u2.f.y; h[6] = u3.f.x; h[7] = u3.f.y;
            const float4 b0 = ((const float4*)s_bias)[2 * q];
            const float4 b1 = ((const float4*)s_bias)[2 * q + 1];
            h[0] = screlu1(h[0] + b0.x); h[1] = screlu1(h[1] + b0.y);
            h[2] = screlu1(h[2] + b0.z); h[3] = screlu1(h[3] + b0.w);
            h[4] = screlu1(h[4] + b1.x); h[5] = screlu1(h[5] + b1.y);
            h[6] = screlu1(h[6] + b1.z); h[7] = screlu1(h[7] + b1.w);
        }

        // pair exchange: partner sample = s^1 -> lane^16
        float p[8];
        #pragma unroll
        for (int k = 0; k < 8; k++)
            p[k] = __shfl_xor_sync(0xffffffffu, h[k], 16);

        int samp = t0 + s;
        if (samp < B) {
            size_t pr = (size_t)(samp >> 1);
            float2* base = ghp + pr * HIDDEN + cbase + 8 * q + odd * 4;
            if (!odd) {
                ((float4*)base)[0] = make_float4(h[0], p[0], h[1], p[1]);
                ((float4*)base)[1] = make_float4(h[2], p[2], h[3], p[3]);
            } else {
                ((float4*)base)[0] = make_float4(p[4], h[4], p[5], h[5]);
                ((float4*)base)[1] = make_float4(p[6], h[6], p[7], h[7]);
            }
        }
        buf ^= 1;
    }
}

// ---------------------------------------------------------------------------
// K2: fc2 via sample-pair FFMA2 with cp.async double-buffered staging; heads.
// (unchanged from R5)
// ---------------------------------------------------------------------------
#define K2_OFF_H    0
#define K2_HBUF     16384
#define K2_OFF_W    32768
#define K2_WBUF     8448
#define K2_OFF_CPW  49664
#define K2_OFF_WDLW 50688
#define K2_OFF_FB   53760
#define K2_OFF_CB   53888
#define K2_OFF_WB   53920
#define K2_OFF_NZ   54016
#define K2_SMEM     54032

__global__ __launch_bounds__(K2T)
void fc_kernel(const void* __restrict__ xv,
               const float* __restrict__ fc2_w, const float* __restrict__ fc2_b,
               const float* __restrict__ cp_w,  const float* __restrict__ cp_b,
               const float* __restrict__ wdl_w, const float* __restrict__ wdl_b,
               const void* __restrict__ pcv, float* __restrict__ out, int B)
{
    extern __shared__ char smem[];
    const uint32_t sbase = smem_u32(smem);

    float* s_cp_w  = (float*)(smem + K2_OFF_CPW);
    float* s_wdl_w = (float*)(smem + K2_OFF_WDLW);
    float* s_fc2_b = (float*)(smem + K2_OFF_FB);
    float* s_cp_b  = (float*)(smem + K2_OFF_CB);
    float* s_wdl_b = (float*)(smem + K2_OFF_WB);
    int*   s_nz    = (int*)(smem + K2_OFF_NZ);

    const int tid = threadIdx.x;
    const int s0  = blockIdx.x * TS2;
    const int p0  = s0 >> 1;

    if (tid == 0) *s_nz = 0;
    __syncthreads();
    if (tid < 64) {
        if (((const unsigned int*)xv)[2 * tid + 1]) atomicOr(s_nz, 1);
    }
    for (int i = tid; i < 8 * 32; i += K2T)  s_cp_w[i]  = cp_w[i];
    for (int i = tid; i < 24 * 32; i += K2T) s_wdl_w[i] = wdl_w[i];
    if (tid < 32) s_fc2_b[tid] = fc2_b[tid];
    if (tid < 8)  s_cp_b[tid]  = cp_b[tid];
    if (tid < 24) s_wdl_b[tid] = wdl_b[tid];

    const float2* ghp = (const float2*)g_h;

    auto stage = [&](int k) {
        int buf = k & 1;
        int c0  = k * CHUNK2;
        uint32_t hdst = sbase + K2_OFF_H + buf * K2_HBUF;
        uint32_t wdst = sbase + K2_OFF_W + buf * K2_WBUF;
        #pragma unroll
        for (int r = 0; r < 4; r++) {
            int u   = tid + r * K2T;
            int p   = u >> 5;
            int c16 = u & 31;
            cp_async16(hdst + (uint32_t)(p * 512 + c16 * 16),
                       ghp + ((size_t)(p0 + p) * HIDDEN + c0 + c16 * 2));
        }
        #pragma unroll
        for (int r = 0; r < 8; r++) {
            int u = tid + r * K2T;
            int j = u >> 6;
            int c = u & 63;
            cp_async4(wdst + (uint32_t)((c * WT_STRIDE + j) * 4),
                      fc2_w + j * HIDDEN + c0 + c);
        }
        CP_COMMIT();
    };

    stage(0);

    const int jq = tid & 15;
    const int sg = tid >> 4;

    unsigned long long acc00 = 0ull, acc01 = 0ull, acc10 = 0ull, acc11 = 0ull;

    for (int k = 0; k < NCHUNKS2; k++) {
        CP_WAIT0();
        __syncthreads();
        if (k + 1 < NCHUNKS2) stage(k + 1);

        int buf = k & 1;
        const unsigned long long* hb =
            (const unsigned long long*)(smem + K2_OFF_H + buf * K2_HBUF);
        const float* wb = (const float*)(smem + K2_OFF_W + buf * K2_WBUF);
        const unsigned long long* h0 = hb + (2 * sg) * CHUNK2;
        const unsigned long long* h1 = hb + (2 * sg + 1) * CHUNK2;

        #pragma unroll 8
        for (int c = 0; c < CHUNK2; c++) {
            unsigned long long hv0 = h0[c];
            unsigned long long hv1 = h1[c];
            unsigned long long W0 = packdup(wb[c * WT_STRIDE + 2 * jq]);
            unsigned long long W1 = packdup(wb[c * WT_STRIDE + 2 * jq + 1]);
            fma2(acc00, hv0, W0);
            fma2(acc01, hv0, W1);
            fma2(acc10, hv1, W0);
            fma2(acc11, hv1, W1);
        }
        __syncthreads();
    }

    float* s_h2 = (float*)(smem + K2_OFF_H);
    {
        unsigned long long accs[2][2] = {{acc00, acc01}, {acc10, acc11}};
        #pragma unroll
        for (int p = 0; p < 2; p++) {
            #pragma unroll
            for (int jj = 0; jj < 2; jj++) {
                int j = 2 * jq + jj;
                float lo = __uint_as_float((unsigned)(accs[p][jj] & 0xffffffffull));
                float hi = __uint_as_float((unsigned)(accs[p][jj] >> 32));
                s_h2[(4 * sg + 2 * p)     * 33 + j] = screlu1(lo + s_fc2_b[j]);
                s_h2[(4 * sg + 2 * p + 1) * 33 + j] = screlu1(hi + s_fc2_b[j]);
            }
        }
    }
    __syncthreads();

    if (tid < TS2) {
        int samp = s0 + tid;
        if (samp < B) {
            const int is64 = (*s_nz == 0);
            int pc = is64 ? (int)((const long long*)pcv)[samp]
                          : ((const int*)pcv)[samp];
            int bkt = (pc - 2) * 8 / 30;
            bkt = max(0, min(7, bkt));

            const float* h2 = &s_h2[tid * 33];
            float cp = s_cp_b[bkt];
            float w0 = s_wdl_b[bkt * 3 + 0];
            float w1 = s_wdl_b[bkt * 3 + 1];
            float w2 = s_wdl_b[bkt * 3 + 2];
            const float* cw  = &s_cp_w[bkt * 32];
            const float* ww0 = &s_wdl_w[(bkt * 3 + 0) * 32];
            const float* ww1 = &s_wdl_w[(bkt * 3 + 1) * 32];
            const float* ww2 = &s_wdl_w[(bkt * 3 + 2) * 32];
            #pragma unroll
            for (int j = 0; j < 32; j++) {
                float hh = h2[j];
                cp = fmaf(hh, cw[j],  cp);
                w0 = fmaf(hh, ww0[j], w0);
                w1 = fmaf(hh, ww1[j], w1);
                w2 = fmaf(hh, ww2[j], w2);
            }
            out[samp] = cp;
            out[B + samp * 3 + 0] = w0;
            out[B + samp * 3 + 1] = w1;
            out[B + samp * 3 + 2] = w2;
        }
    }
}

// ---------------------------------------------------------------------------
extern "C" void kernel_launch(void* const* d_in, const int* in_sizes, int n_in,
                              void* d_out, int out_size)
{
    const void*  x      = d_in[0];
    const void*  pc     = d_in[1];
    const float* emb    = (const float*)d_in[2];
    const float* bias1  = (const float*)d_in[3];
    const float* fc2_w  = (const float*)d_in[4];
    const float* fc2_b  = (const float*)d_in[5];
    const float* cp_w   = (const float*)d_in[6];
    const float* cp_b   = (const float*)d_in[7];
    const float* wdl_w  = (const float*)d_in[8];
    const float* wdl_b  = (const float*)d_in[9];

    int B = in_sizes[0] / 32;
    if (B > MAX_B) B = MAX_B;

    // K0: fp16 table build (769*1024/2 half2 / 512 threads = 769 blocks)
    convert_kernel<<<NROWS, 512>>>(emb);

    // K1
    const int k1_smem = NROWS * CHUNK1 * 2 + 8192 + CHUNK1 * 4 + 16;
    cudaFuncSetAttribute(gather_kernel,
                         cudaFuncAttributeMaxDynamicSharedMemorySize, k1_smem);
    dim3 g1(NCHUNKS1, NGROUPS1);
    gather_kernel<<<g1, K1T, k1_smem>>>(x, bias1, B);

    // K2
    cudaFuncSetAttribute(fc_kernel,
                         cudaFuncAttributeMaxDynamicSharedMemorySize, K2_SMEM);
    int g2 = (B + TS2 - 1) / TS2;
    fc_kernel<<<g2, K2T, K2_SMEM>>>(x, fc2_w, fc2_b, cp_w, cp_b, wdl_w, wdl_b,
                                    pc, (float*)d_out, B);
}